// round 1
// baseline (speedup 1.0000x reference)
#include <cuda_runtime.h>

#define REPS 1e-4f

// Scratch (no allocations allowed)
__device__ float g_M[25];    // M = W1^T X W1 accumulator
__device__ float g_A5[25];   // A5 = U*(max(sqrt(lam),EPS)-EPS)*U^T

// ---------------------------------------------------------------------------
// K0: zero the M accumulator (graph replays must reset state)
// ---------------------------------------------------------------------------
__global__ void k_zero() {
    if (threadIdx.x < 25) g_M[threadIdx.x] = 0.f;
}

// ---------------------------------------------------------------------------
// KA: M[a][b] = sum_{i,j} W1[i,a] * X[i,j] * W1[j,b]
// Block: 256 threads, 2048-col tile (8 cols/thread as 2x float4), 32 rows.
// Grid: (2, 128). Per-thread: pacc[b] over its 8 cols per row (5 FMA/elem),
// then 25 FMA per row to fold in W1[i,a]. W1 cols cached in registers.
// ---------------------------------------------------------------------------
__global__ __launch_bounds__(256) void k_proj(const float* __restrict__ X,
                                              const float* __restrict__ W1) {
    const int tid   = threadIdx.x;
    const int jbase = blockIdx.x * 2048 + tid * 4;   // cols jbase..+3 and +1024..+1027
    const int ibase = blockIdx.y * 32;

    // Cache this thread's 8 W1 column-rows (40 regs)
    float w1c[8][5];
#pragma unroll
    for (int grp = 0; grp < 2; grp++) {
#pragma unroll
        for (int c = 0; c < 4; c++) {
            const int j = jbase + grp * 1024 + c;
#pragma unroll
            for (int b = 0; b < 5; b++) w1c[grp * 4 + c][b] = W1[j * 5 + b];
        }
    }

    float Mp[5][5];
#pragma unroll
    for (int a = 0; a < 5; a++)
#pragma unroll
        for (int b = 0; b < 5; b++) Mp[a][b] = 0.f;

#pragma unroll 4
    for (int r = 0; r < 32; r++) {
        const int i = ibase + r;
        const float4 xA = *reinterpret_cast<const float4*>(X + (size_t)i * 4096 + jbase);
        const float4 xB = *reinterpret_cast<const float4*>(X + (size_t)i * 4096 + jbase + 1024);
        const float xv[8] = {xA.x, xA.y, xA.z, xA.w, xB.x, xB.y, xB.z, xB.w};

        float p[5] = {0.f, 0.f, 0.f, 0.f, 0.f};
#pragma unroll
        for (int c = 0; c < 8; c++)
#pragma unroll
            for (int b = 0; b < 5; b++) p[b] += xv[c] * w1c[c][b];

        float w1i[5];
#pragma unroll
        for (int a = 0; a < 5; a++) w1i[a] = W1[i * 5 + a];   // uniform -> L1 broadcast
#pragma unroll
        for (int a = 0; a < 5; a++)
#pragma unroll
            for (int b = 0; b < 5; b++) Mp[a][b] += w1i[a] * p[b];
    }

    // Reduce 25 values: warp shuffle -> shared -> 25 global atomics per block
    __shared__ float sM[8][25];
    const int lane = tid & 31, warp = tid >> 5;
#pragma unroll
    for (int e = 0; e < 25; e++) {
        float v = Mp[e / 5][e % 5];
#pragma unroll
        for (int o = 16; o > 0; o >>= 1) v += __shfl_down_sync(0xffffffffu, v, o);
        if (lane == 0) sM[warp][e] = v;
    }
    __syncthreads();
    if (tid < 25) {
        float v = 0.f;
#pragma unroll
        for (int w = 0; w < 8; w++) v += sM[w][tid];
        atomicAdd(&g_M[tid], v);
    }
}

// ---------------------------------------------------------------------------
// KB: B = M*M^T ; Jacobi eigendecomposition B = U diag(lam) U^T ;
//     A5 = U * diag(max(sqrt(lam),EPS) - EPS) * U^T
// Single thread, fully unrolled (all indices compile-time => registers).
// ---------------------------------------------------------------------------
__global__ void k_eig() {
    if (threadIdx.x != 0) return;
    float m[5][5], b[5][5], u[5][5];
#pragma unroll
    for (int a = 0; a < 5; a++)
#pragma unroll
        for (int c = 0; c < 5; c++) m[a][c] = g_M[a * 5 + c];

#pragma unroll
    for (int a = 0; a < 5; a++)
#pragma unroll
        for (int c = 0; c < 5; c++) {
            float s = 0.f;
#pragma unroll
            for (int k = 0; k < 5; k++) s += m[a][k] * m[c][k];
            b[a][c] = s;
            u[a][c] = (a == c) ? 1.f : 0.f;
        }

#pragma unroll
    for (int sweep = 0; sweep < 8; sweep++) {
#pragma unroll
        for (int p = 0; p < 4; p++) {
#pragma unroll
            for (int q = p + 1; q < 5; q++) {
                const float apq = b[p][q];
                if (fabsf(apq) > 1e-20f) {
                    const float tau = (b[q][q] - b[p][p]) / (2.f * apq);
                    const float t   = copysignf(1.f, tau) / (fabsf(tau) + sqrtf(1.f + tau * tau));
                    const float c   = rsqrtf(1.f + t * t);
                    const float s   = t * c;
                    // B <- B*J (columns p,q)
#pragma unroll
                    for (int k = 0; k < 5; k++) {
                        const float bkp = b[k][p], bkq = b[k][q];
                        b[k][p] = c * bkp - s * bkq;
                        b[k][q] = s * bkp + c * bkq;
                    }
                    // B <- J^T*B (rows p,q), U <- U*J
#pragma unroll
                    for (int k = 0; k < 5; k++) {
                        const float bpk = b[p][k], bqk = b[q][k];
                        b[p][k] = c * bpk - s * bqk;
                        b[q][k] = s * bpk + c * bqk;
                        const float ukp = u[k][p], ukq = u[k][q];
                        u[k][p] = c * ukp - s * ukq;
                        u[k][q] = s * ukp + c * ukq;
                    }
                }
            }
        }
    }

    float f[5];
#pragma unroll
    for (int i = 0; i < 5; i++) {
        const float lam = fmaxf(b[i][i], 0.f);
        f[i] = fmaxf(sqrtf(lam), REPS) - REPS;
    }
#pragma unroll
    for (int a = 0; a < 5; a++)
#pragma unroll
        for (int c = 0; c < 5; c++) {
            float s = 0.f;
#pragma unroll
            for (int i = 0; i < 5; i++) s += u[a][i] * f[i] * u[c][i];
            g_A5[a * 5 + c] = s;
        }
}

// ---------------------------------------------------------------------------
// KC: z[i][j] = sum_a W2[a,i] * G[a,j] + EPS*(i==j),  G = A5 @ W2
// Block: 256 threads, 1024-col tile (4 cols/thread as float4), 16 rows.
// Grid: (2, 128). Store-bound (16 MB).
// ---------------------------------------------------------------------------
__global__ __launch_bounds__(256) void k_out(const float* __restrict__ W2,
                                             float* __restrict__ out) {
    const int tid   = threadIdx.x;
    const int j0    = blockIdx.x * 1024 + tid * 4;
    const int ibase = blockIdx.y * 16;

    float a5[5][5];
#pragma unroll
    for (int a = 0; a < 5; a++)
#pragma unroll
        for (int c = 0; c < 5; c++) a5[a][c] = g_A5[a * 5 + c];

    float gv[5][4];
#pragma unroll
    for (int cc = 0; cc < 4; cc++) {
        float w2j[5];
#pragma unroll
        for (int b2 = 0; b2 < 5; b2++) w2j[b2] = W2[b2 * 2048 + j0 + cc];
#pragma unroll
        for (int a = 0; a < 5; a++) {
            float s = 0.f;
#pragma unroll
            for (int b2 = 0; b2 < 5; b2++) s += a5[a][b2] * w2j[b2];
            gv[a][cc] = s;
        }
    }

#pragma unroll 4
    for (int r = 0; r < 16; r++) {
        const int i = ibase + r;
        float w2i[5];
#pragma unroll
        for (int a = 0; a < 5; a++) w2i[a] = W2[a * 2048 + i];  // uniform -> broadcast
        float vv[4];
#pragma unroll
        for (int cc = 0; cc < 4; cc++) {
            float s = 0.f;
#pragma unroll
            for (int a = 0; a < 5; a++) s += w2i[a] * gv[a][cc];
            if (i == j0 + cc) s += REPS;
            vv[cc] = s;
        }
        float4 v;
        v.x = vv[0]; v.y = vv[1]; v.z = vv[2]; v.w = vv[3];
        *reinterpret_cast<float4*>(out + (size_t)i * 2048 + j0) = v;
    }
}

// ---------------------------------------------------------------------------
extern "C" void kernel_launch(void* const* d_in, const int* in_sizes, int n_in,
                              void* d_out, int out_size) {
    const float* X  = (const float*)d_in[0];   // (1, 4096, 4096) f32
    const float* W1 = (const float*)d_in[1];   // (4096, 5) f32
    const float* W2 = (const float*)d_in[2];   // (5, 2048) f32
    float* out = (float*)d_out;                // (2048, 2048) f32

    k_zero<<<1, 32>>>();
    k_proj<<<dim3(2, 128), 256>>>(X, W1);
    k_eig<<<1, 32>>>();
    k_out<<<dim3(2, 128), 256>>>(W2, out);
}

// round 2
// speedup vs baseline: 1.1707x; 1.1707x over previous
#include <cuda_runtime.h>

#define REPS 1e-4f
#define GY 148   // one block-row per SM; grid (2, GY) = 2 blocks per SM

// Scratch (no allocations allowed). Zero-initialized at module load; the
// last block of k_proj resets them after consuming, so graph replays see
// clean state.
__device__ float    g_M[25 * 32];  // each accumulator on its own 128B line
__device__ unsigned g_cnt;
__device__ float    g_A5[25];      // A5 = U*(max(sqrt(lam),EPS)-EPS)*U^T

// ---------------------------------------------------------------------------
// K1 (fused): M[a][b] = sum_{i,j} W1[i,a] * X[i,j] * W1[j,b], then the LAST
// block runs the 5x5 eigensolve and emits g_A5 (and resets scratch).
// Block: 256 threads; covers 2048 cols (tid*4 and +1024), rows grid-strided.
// ---------------------------------------------------------------------------
__global__ __launch_bounds__(256) void k_proj(const float* __restrict__ X,
                                              const float* __restrict__ W1) {
    const int tid   = threadIdx.x;
    const int jbase = blockIdx.x * 2048 + tid * 4;

    // Cache this thread's 8 W1 column-rows (40 regs)
    float w1c[8][5];
#pragma unroll
    for (int grp = 0; grp < 2; grp++)
#pragma unroll
        for (int c = 0; c < 4; c++) {
            const int j = jbase + grp * 1024 + c;
#pragma unroll
            for (int b = 0; b < 5; b++) w1c[grp * 4 + c][b] = __ldg(W1 + j * 5 + b);
        }

    float Mp[5][5];
#pragma unroll
    for (int a = 0; a < 5; a++)
#pragma unroll
        for (int b = 0; b < 5; b++) Mp[a][b] = 0.f;

    // Rows grid-strided by GY with depth-1 software prefetch (2 rows in flight)
    int i = blockIdx.y;
    float4 curA = *reinterpret_cast<const float4*>(X + (size_t)i * 4096 + jbase);
    float4 curB = *reinterpret_cast<const float4*>(X + (size_t)i * 4096 + jbase + 1024);
    int inext = i + GY;
    float4 nxtA, nxtB;
    if (inext < 4096) {
        nxtA = *reinterpret_cast<const float4*>(X + (size_t)inext * 4096 + jbase);
        nxtB = *reinterpret_cast<const float4*>(X + (size_t)inext * 4096 + jbase + 1024);
    }
    while (true) {
        const float xv[8] = {curA.x, curA.y, curA.z, curA.w,
                             curB.x, curB.y, curB.z, curB.w};
        float p[5] = {0.f, 0.f, 0.f, 0.f, 0.f};
#pragma unroll
        for (int c = 0; c < 8; c++)
#pragma unroll
            for (int b = 0; b < 5; b++) p[b] += xv[c] * w1c[c][b];

        float w1i[5];
#pragma unroll
        for (int a = 0; a < 5; a++) w1i[a] = __ldg(W1 + i * 5 + a);  // broadcast
#pragma unroll
        for (int a = 0; a < 5; a++)
#pragma unroll
            for (int b = 0; b < 5; b++) Mp[a][b] += w1i[a] * p[b];

        if (inext >= 4096) break;
        i = inext; curA = nxtA; curB = nxtB;
        inext = i + GY;
        if (inext < 4096) {
            nxtA = *reinterpret_cast<const float4*>(X + (size_t)inext * 4096 + jbase);
            nxtB = *reinterpret_cast<const float4*>(X + (size_t)inext * 4096 + jbase + 1024);
        }
    }

    // Reduce 25 values: warp shuffle -> shared -> 25 padded global atomics
    __shared__ float sM[8][25];
    __shared__ bool  sLast;
    const int lane = tid & 31, warp = tid >> 5;
#pragma unroll
    for (int e = 0; e < 25; e++) {
        float v = Mp[e / 5][e % 5];
#pragma unroll
        for (int o = 16; o > 0; o >>= 1) v += __shfl_down_sync(0xffffffffu, v, o);
        if (lane == 0) sM[warp][e] = v;
    }
    __syncthreads();
    if (tid < 25) {
        float v = 0.f;
#pragma unroll
        for (int w = 0; w < 8; w++) v += sM[w][tid];
        atomicAdd(&g_M[tid * 32], v);   // each element on its own 128B line
    }
    if (tid == 0) {
        __threadfence();
        sLast = (atomicAdd(&g_cnt, 1u) == 2u * GY - 1u);
    }
    __syncthreads();
    if (!sLast || tid != 0) return;

    // ---- Last block, single thread: B = M*M^T ; Jacobi ; emit A5 ----
    float m[5][5], b[5][5], u[5][5];
#pragma unroll
    for (int a = 0; a < 5; a++)
#pragma unroll
        for (int c = 0; c < 5; c++) m[a][c] = __ldcg(&g_M[(a * 5 + c) * 32]);

#pragma unroll
    for (int a = 0; a < 5; a++)
#pragma unroll
        for (int c = 0; c < 5; c++) {
            float s = 0.f;
#pragma unroll
            for (int k = 0; k < 5; k++) s += m[a][k] * m[c][k];
            b[a][c] = s;
            u[a][c] = (a == c) ? 1.f : 0.f;
        }

#pragma unroll
    for (int sweep = 0; sweep < 6; sweep++) {
#pragma unroll
        for (int p = 0; p < 4; p++) {
#pragma unroll
            for (int q = p + 1; q < 5; q++) {
                const float apq = b[p][q];
                if (fabsf(apq) > 1e-20f) {
                    const float tau = (b[q][q] - b[p][p]) / (2.f * apq);
                    const float t   = copysignf(1.f, tau) / (fabsf(tau) + sqrtf(1.f + tau * tau));
                    const float c   = rsqrtf(1.f + t * t);
                    const float s   = t * c;
#pragma unroll
                    for (int k = 0; k < 5; k++) {
                        const float bkp = b[k][p], bkq = b[k][q];
                        b[k][p] = c * bkp - s * bkq;
                        b[k][q] = s * bkp + c * bkq;
                    }
#pragma unroll
                    for (int k = 0; k < 5; k++) {
                        const float bpk = b[p][k], bqk = b[q][k];
                        b[p][k] = c * bpk - s * bqk;
                        b[q][k] = s * bpk + c * bqk;
                        const float ukp = u[k][p], ukq = u[k][q];
                        u[k][p] = c * ukp - s * ukq;
                        u[k][q] = s * ukp + c * ukq;
                    }
                }
            }
        }
    }

    float f[5];
#pragma unroll
    for (int d = 0; d < 5; d++) {
        const float lam = fmaxf(b[d][d], 0.f);
        f[d] = fmaxf(sqrtf(lam), REPS) - REPS;
    }
#pragma unroll
    for (int a = 0; a < 5; a++)
#pragma unroll
        for (int c = 0; c < 5; c++) {
            float s = 0.f;
#pragma unroll
            for (int d = 0; d < 5; d++) s += u[a][d] * f[d] * u[c][d];
            g_A5[a * 5 + c] = s;
        }

    // Reset scratch for the next graph replay
#pragma unroll
    for (int e = 0; e < 25; e++) g_M[e * 32] = 0.f;
    g_cnt = 0u;
}

// ---------------------------------------------------------------------------
// K2: z[i][j] = sum_a W2[a,i] * G[a,j] + EPS*(i==j),  G = A5 @ W2
// Block: 256 threads, 1024 cols (tid*4), rows grid-strided by GY.
// Grid (2, GY) = 296 blocks, 2/SM, balanced.
// ---------------------------------------------------------------------------
__global__ __launch_bounds__(256) void k_out(const float* __restrict__ W2,
                                             float* __restrict__ out) {
    const int tid = threadIdx.x;
    const int j0  = blockIdx.x * 1024 + tid * 4;

    float a5[5][5];
#pragma unroll
    for (int a = 0; a < 5; a++)
#pragma unroll
        for (int c = 0; c < 5; c++) a5[a][c] = g_A5[a * 5 + c];

    float gv[5][4];
#pragma unroll
    for (int cc = 0; cc < 4; cc++) {
        float w2j[5];
#pragma unroll
        for (int b2 = 0; b2 < 5; b2++) w2j[b2] = __ldg(W2 + b2 * 2048 + j0 + cc);
#pragma unroll
        for (int a = 0; a < 5; a++) {
            float s = 0.f;
#pragma unroll
            for (int b2 = 0; b2 < 5; b2++) s += a5[a][b2] * w2j[b2];
            gv[a][cc] = s;
        }
    }

    for (int i = blockIdx.y; i < 2048; i += GY) {
        float w2i[5];
#pragma unroll
        for (int a = 0; a < 5; a++) w2i[a] = __ldg(W2 + a * 2048 + i);  // broadcast
        float vv[4];
#pragma unroll
        for (int cc = 0; cc < 4; cc++) {
            float s = 0.f;
#pragma unroll
            for (int a = 0; a < 5; a++) s += w2i[a] * gv[a][cc];
            if (i == j0 + cc) s += REPS;
            vv[cc] = s;
        }
        float4 v;
        v.x = vv[0]; v.y = vv[1]; v.z = vv[2]; v.w = vv[3];
        *reinterpret_cast<float4*>(out + (size_t)i * 2048 + j0) = v;
    }
}

// ---------------------------------------------------------------------------
extern "C" void kernel_launch(void* const* d_in, const int* in_sizes, int n_in,
                              void* d_out, int out_size) {
    const float* X  = (const float*)d_in[0];   // (1, 4096, 4096) f32
    const float* W1 = (const float*)d_in[1];   // (4096, 5) f32
    const float* W2 = (const float*)d_in[2];   // (5, 2048) f32
    float* out = (float*)d_out;                // (2048, 2048) f32

    k_proj<<<dim3(2, GY), 256>>>(X, W1);
    k_out <<<dim3(2, GY), 256>>>(W2, out);
}

// round 3
// speedup vs baseline: 1.3672x; 1.1679x over previous
#include <cuda_runtime.h>

#define REPS 1e-4f
#define GYP 148          // k_proj row stride / grid.y
#define NBLK_PROJ (4 * GYP)

// Scratch (no allocations allowed). Zero-init at load; last k_proj block
// resets after consuming so graph replays see clean state.
__device__ float    g_M[25 * 32];  // each accumulator on its own 128B line
__device__ unsigned g_cnt;
__device__ float    g_A5[25];      // A5 = U*(max(sqrt(lam),EPS)-EPS)*U^T

// ---------------------------------------------------------------------------
// K1: column-major reduction.  Thread owns 4 columns j; accumulates
//   tacc[cc][a] += X[i][j+cc] * W1[i][a]   (W1 row broadcast-loaded)
// over all rows, then folds M[a][b] += tacc[cc][a]*W1[j+cc][b] ONCE at the
// end, block-reduces 25 values, atomicAdd to padded lines. Last block runs
// the 5x5 Jacobi eigensolve and emits g_A5.
// Registers ~40 -> 4 blocks/SM -> 1024 thr/SM, deep MLP.
// ---------------------------------------------------------------------------
__global__ __launch_bounds__(256, 4) void k_proj(const float* __restrict__ X,
                                                 const float* __restrict__ W1) {
    const int tid = threadIdx.x;
    const int j0  = blockIdx.x * 1024 + tid * 4;

    float tacc[4][5];
#pragma unroll
    for (int cc = 0; cc < 4; cc++)
#pragma unroll
        for (int a = 0; a < 5; a++) tacc[cc][a] = 0.f;

    // depth-2 software pipeline over rows i = blockIdx.y, +GYP, ...
    int i = blockIdx.y;
    float4 x = __ldcs(reinterpret_cast<const float4*>(X + (size_t)i * 4096 + j0));
    float w[5];
#pragma unroll
    for (int a = 0; a < 5; a++) w[a] = __ldg(W1 + i * 5 + a);

    while (true) {
        const int inext = i + GYP;
        float4 xn;
        float  wn[5];
        const bool more = (inext < 4096);
        if (more) {
            xn = __ldcs(reinterpret_cast<const float4*>(X + (size_t)inext * 4096 + j0));
#pragma unroll
            for (int a = 0; a < 5; a++) wn[a] = __ldg(W1 + inext * 5 + a);
        }
        const float xv[4] = {x.x, x.y, x.z, x.w};
#pragma unroll
        for (int cc = 0; cc < 4; cc++)
#pragma unroll
            for (int a = 0; a < 5; a++) tacc[cc][a] += xv[cc] * w[a];
        if (!more) break;
        i = inext; x = xn;
#pragma unroll
        for (int a = 0; a < 5; a++) w[a] = wn[a];
    }

    // Fold with W1[j,b] once
    float mp[5][5];
#pragma unroll
    for (int a = 0; a < 5; a++)
#pragma unroll
        for (int b = 0; b < 5; b++) mp[a][b] = 0.f;
#pragma unroll
    for (int cc = 0; cc < 4; cc++) {
        float w1j[5];
#pragma unroll
        for (int b = 0; b < 5; b++) w1j[b] = __ldg(W1 + (j0 + cc) * 5 + b);
#pragma unroll
        for (int a = 0; a < 5; a++)
#pragma unroll
            for (int b = 0; b < 5; b++) mp[a][b] += tacc[cc][a] * w1j[b];
    }

    // Block reduce 25 values: warp shuffle -> shared -> 25 padded atomics
    __shared__ float sM[8][25];
    __shared__ bool  sLast;
    const int lane = tid & 31, warp = tid >> 5;
#pragma unroll
    for (int e = 0; e < 25; e++) {
        float v = mp[e / 5][e % 5];
#pragma unroll
        for (int o = 16; o > 0; o >>= 1) v += __shfl_down_sync(0xffffffffu, v, o);
        if (lane == 0) sM[warp][e] = v;
    }
    __syncthreads();
    if (tid < 25) {
        float v = 0.f;
#pragma unroll
        for (int wq = 0; wq < 8; wq++) v += sM[wq][tid];
        atomicAdd(&g_M[tid * 32], v);
    }
    if (tid == 0) {
        __threadfence();
        sLast = (atomicAdd(&g_cnt, 1u) == (unsigned)NBLK_PROJ - 1u);
    }
    __syncthreads();
    if (!sLast || tid != 0) return;

    // ---- Last block, single thread: B = M*M^T ; Jacobi ; emit A5 ----
    float m[5][5], b[5][5], u[5][5];
#pragma unroll
    for (int a = 0; a < 5; a++)
#pragma unroll
        for (int c = 0; c < 5; c++) m[a][c] = __ldcg(&g_M[(a * 5 + c) * 32]);

    float tr = 0.f;
#pragma unroll
    for (int a = 0; a < 5; a++)
#pragma unroll
        for (int c = 0; c < 5; c++) {
            float s = 0.f;
#pragma unroll
            for (int k = 0; k < 5; k++) s += m[a][k] * m[c][k];
            b[a][c] = s;
            u[a][c] = (a == c) ? 1.f : 0.f;
            if (a == c) tr += s;
        }
    const float skip_tol = 1e-7f * tr;   // relative convergence threshold

#pragma unroll
    for (int sweep = 0; sweep < 5; sweep++) {
#pragma unroll
        for (int p = 0; p < 4; p++) {
#pragma unroll
            for (int q = p + 1; q < 5; q++) {
                const float apq = b[p][q];
                if (fabsf(apq) > skip_tol) {
                    const float tau = (b[q][q] - b[p][p]) / (2.f * apq);
                    const float t   = copysignf(1.f, tau) / (fabsf(tau) + sqrtf(1.f + tau * tau));
                    const float c   = rsqrtf(1.f + t * t);
                    const float s   = t * c;
#pragma unroll
                    for (int k = 0; k < 5; k++) {
                        const float bkp = b[k][p], bkq = b[k][q];
                        b[k][p] = c * bkp - s * bkq;
                        b[k][q] = s * bkp + c * bkq;
                    }
#pragma unroll
                    for (int k = 0; k < 5; k++) {
                        const float bpk = b[p][k], bqk = b[q][k];
                        b[p][k] = c * bpk - s * bqk;
                        b[q][k] = s * bpk + c * bqk;
                        const float ukp = u[k][p], ukq = u[k][q];
                        u[k][p] = c * ukp - s * ukq;
                        u[k][q] = s * ukp + c * ukq;
                    }
                }
            }
        }
    }

    float f[5];
#pragma unroll
    for (int d = 0; d < 5; d++) {
        const float lam = fmaxf(b[d][d], 0.f);
        f[d] = fmaxf(sqrtf(lam), REPS) - REPS;
    }
#pragma unroll
    for (int a = 0; a < 5; a++)
#pragma unroll
        for (int c = 0; c < 5; c++) {
            float s = 0.f;
#pragma unroll
            for (int d = 0; d < 5; d++) s += u[a][d] * f[d] * u[c][d];
            g_A5[a * 5 + c] = s;
        }

    // Reset scratch for the next graph replay
#pragma unroll
    for (int e = 0; e < 25; e++) g_M[e * 32] = 0.f;
    g_cnt = 0u;
}

// ---------------------------------------------------------------------------
// K2: z[i][j] = sum_a W2[a,i] * H[a,j] + EPS*(i==j),  H = A5 @ W2
// Each block recomputes its own H slice (trivial). Grid (2,296)=592 blocks,
// 4/SM single wave. Thread: 1 float4 of j, rows strided by 296.
// ---------------------------------------------------------------------------
__global__ __launch_bounds__(256, 4) void k_out(const float* __restrict__ W2,
                                                float* __restrict__ out) {
    const int tid = threadIdx.x;
    const int j0  = blockIdx.x * 1024 + tid * 4;

    float hv[5][4];
    {
        float a5[5][5];
#pragma unroll
        for (int a = 0; a < 5; a++)
#pragma unroll
            for (int c = 0; c < 5; c++) a5[a][c] = g_A5[a * 5 + c];
#pragma unroll
        for (int cc = 0; cc < 4; cc++) {
            float w2j[5];
#pragma unroll
            for (int b2 = 0; b2 < 5; b2++) w2j[b2] = __ldg(W2 + b2 * 2048 + j0 + cc);
#pragma unroll
            for (int a = 0; a < 5; a++) {
                float s = 0.f;
#pragma unroll
                for (int b2 = 0; b2 < 5; b2++) s += a5[a][b2] * w2j[b2];
                hv[a][cc] = s;
            }
        }
    }

    for (int i = blockIdx.y; i < 2048; i += 296) {
        float w2i[5];
#pragma unroll
        for (int a = 0; a < 5; a++) w2i[a] = __ldg(W2 + a * 2048 + i);  // broadcast
        float vv[4];
#pragma unroll
        for (int cc = 0; cc < 4; cc++) {
            float s = 0.f;
#pragma unroll
            for (int a = 0; a < 5; a++) s += w2i[a] * hv[a][cc];
            if (i == j0 + cc) s += REPS;
            vv[cc] = s;
        }
        float4 v;
        v.x = vv[0]; v.y = vv[1]; v.z = vv[2]; v.w = vv[3];
        *reinterpret_cast<float4*>(out + (size_t)i * 2048 + j0) = v;
    }
}

// ---------------------------------------------------------------------------
extern "C" void kernel_launch(void* const* d_in, const int* in_sizes, int n_in,
                              void* d_out, int out_size) {
    const float* X  = (const float*)d_in[0];   // (1, 4096, 4096) f32
    const float* W1 = (const float*)d_in[1];   // (4096, 5) f32
    const float* W2 = (const float*)d_in[2];   // (5, 2048) f32
    float* out = (float*)d_out;                // (2048, 2048) f32

    k_proj<<<dim3(4, GYP), 256>>>(X, W1);
    k_out <<<dim3(2, 296), 256>>>(W2, out);
}

// round 4
// speedup vs baseline: 1.4545x; 1.0639x over previous
#include <cuda_runtime.h>

#define REPS 1e-4f
#define GYP 148
#define NBLK_PROJ (4 * GYP)

// Scratch (no allocations allowed). Zero-init at load; last k_proj block
// resets g_M/g_cnt after consuming, so graph replays see clean state.
__device__ float    g_M[25 * 32];  // each accumulator on its own 128B line
__device__ unsigned g_cnt;
__device__ float    g_H[5 * 2048]; // H = A5 @ W2, produced by last proj block

// ---------------------------------------------------------------------------
// K1: t[j][a] = sum_i W1[i,a]*X[i,j]; fold M[a][b] += t[j][a]*W1[j,b] once.
// Block: 256 thr, 1024-col x-tile (4 cols/thread), contiguous row band
// [r0,r1) with W1 rows staged in shared (kills scalar-LDG wavefront storm).
// Inner loop unrolled x4 with front-batched LDG.128 (64B/thread in flight).
// Last block: 5x5 Jacobi (thread 0) then cooperative H = A5@W2 to g_H.
// ---------------------------------------------------------------------------
__global__ __launch_bounds__(256, 4) void k_proj(const float* __restrict__ X,
                                                 const float* __restrict__ W1,
                                                 const float* __restrict__ W2) {
    const int tid = threadIdx.x;
    const int j0  = blockIdx.x * 1024 + tid * 4;
    const int r0  = (blockIdx.y * 4096) / GYP;
    const int r1  = ((blockIdx.y + 1) * 4096) / GYP;
    const int R   = r1 - r0;                      // 27 or 28

    __shared__ float sW1[28 * 5];
    __shared__ float sM[8][25];
    __shared__ float sA5[25];
    __shared__ bool  sLast;
    if (tid < R * 5) sW1[tid] = W1[r0 * 5 + tid];
    __syncthreads();

    float tacc[4][5];
#pragma unroll
    for (int cc = 0; cc < 4; cc++)
#pragma unroll
        for (int a = 0; a < 5; a++) tacc[cc][a] = 0.f;

    const float* Xb = X + (size_t)r0 * 4096 + j0;
    int r = 0;
    for (; r + 4 <= R; r += 4) {
        const float4 x0 = __ldcs(reinterpret_cast<const float4*>(Xb + (size_t)(r + 0) * 4096));
        const float4 x1 = __ldcs(reinterpret_cast<const float4*>(Xb + (size_t)(r + 1) * 4096));
        const float4 x2 = __ldcs(reinterpret_cast<const float4*>(Xb + (size_t)(r + 2) * 4096));
        const float4 x3 = __ldcs(reinterpret_cast<const float4*>(Xb + (size_t)(r + 3) * 4096));
        const float4 xs[4] = {x0, x1, x2, x3};
#pragma unroll
        for (int k = 0; k < 4; k++) {
            const float xv[4] = {xs[k].x, xs[k].y, xs[k].z, xs[k].w};
            float w[5];
#pragma unroll
            for (int a = 0; a < 5; a++) w[a] = sW1[(r + k) * 5 + a];
#pragma unroll
            for (int cc = 0; cc < 4; cc++)
#pragma unroll
                for (int a = 0; a < 5; a++) tacc[cc][a] += xv[cc] * w[a];
        }
    }
    for (; r < R; r++) {
        const float4 x = __ldcs(reinterpret_cast<const float4*>(Xb + (size_t)r * 4096));
        const float xv[4] = {x.x, x.y, x.z, x.w};
        float w[5];
#pragma unroll
        for (int a = 0; a < 5; a++) w[a] = sW1[r * 5 + a];
#pragma unroll
        for (int cc = 0; cc < 4; cc++)
#pragma unroll
            for (int a = 0; a < 5; a++) tacc[cc][a] += xv[cc] * w[a];
    }

    // Fold with W1[j,b] once per thread
    float mp[5][5];
#pragma unroll
    for (int a = 0; a < 5; a++)
#pragma unroll
        for (int b = 0; b < 5; b++) mp[a][b] = 0.f;
#pragma unroll
    for (int cc = 0; cc < 4; cc++) {
        float w1j[5];
#pragma unroll
        for (int b = 0; b < 5; b++) w1j[b] = __ldg(W1 + (j0 + cc) * 5 + b);
#pragma unroll
        for (int a = 0; a < 5; a++)
#pragma unroll
            for (int b = 0; b < 5; b++) mp[a][b] += tacc[cc][a] * w1j[b];
    }

    // Block reduce 25 values -> 25 padded global atomics
    const int lane = tid & 31, warp = tid >> 5;
#pragma unroll
    for (int e = 0; e < 25; e++) {
        float v = mp[e / 5][e % 5];
#pragma unroll
        for (int o = 16; o > 0; o >>= 1) v += __shfl_down_sync(0xffffffffu, v, o);
        if (lane == 0) sM[warp][e] = v;
    }
    __syncthreads();
    if (tid < 25) {
        float v = 0.f;
#pragma unroll
        for (int wq = 0; wq < 8; wq++) v += sM[wq][tid];
        atomicAdd(&g_M[tid * 32], v);
    }
    if (tid == 0) {
        __threadfence();
        sLast = (atomicAdd(&g_cnt, 1u) == (unsigned)NBLK_PROJ - 1u);
    }
    __syncthreads();
    if (!sLast) return;

    // ---- Last block. Thread 0: B = M*M^T ; Jacobi ; A5 -> shared ----
    if (tid == 0) {
        float m[5][5], b[5][5], u[5][5];
#pragma unroll
        for (int a = 0; a < 5; a++)
#pragma unroll
            for (int c = 0; c < 5; c++) m[a][c] = __ldcg(&g_M[(a * 5 + c) * 32]);

        float tr = 0.f;
#pragma unroll
        for (int a = 0; a < 5; a++)
#pragma unroll
            for (int c = 0; c < 5; c++) {
                float s = 0.f;
#pragma unroll
                for (int k = 0; k < 5; k++) s += m[a][k] * m[c][k];
                b[a][c] = s;
                u[a][c] = (a == c) ? 1.f : 0.f;
                if (a == c) tr += s;
            }
        const float skip_tol = 1e-7f * tr;

#pragma unroll
        for (int sweep = 0; sweep < 5; sweep++) {
#pragma unroll
            for (int p = 0; p < 4; p++) {
#pragma unroll
                for (int q = p + 1; q < 5; q++) {
                    const float apq = b[p][q];
                    if (fabsf(apq) > skip_tol) {
                        const float tau = (b[q][q] - b[p][p]) / (2.f * apq);
                        const float t   = copysignf(1.f, tau) / (fabsf(tau) + sqrtf(1.f + tau * tau));
                        const float c   = rsqrtf(1.f + t * t);
                        const float s   = t * c;
#pragma unroll
                        for (int k = 0; k < 5; k++) {
                            const float bkp = b[k][p], bkq = b[k][q];
                            b[k][p] = c * bkp - s * bkq;
                            b[k][q] = s * bkp + c * bkq;
                        }
#pragma unroll
                        for (int k = 0; k < 5; k++) {
                            const float bpk = b[p][k], bqk = b[q][k];
                            b[p][k] = c * bpk - s * bqk;
                            b[q][k] = s * bpk + c * bqk;
                            const float ukp = u[k][p], ukq = u[k][q];
                            u[k][p] = c * ukp - s * ukq;
                            u[k][q] = s * ukp + c * ukq;
                        }
                    }
                }
            }
        }

        float f[5];
#pragma unroll
        for (int d = 0; d < 5; d++) {
            const float lam = fmaxf(b[d][d], 0.f);
            f[d] = fmaxf(sqrtf(lam), REPS) - REPS;
        }
#pragma unroll
        for (int a = 0; a < 5; a++)
#pragma unroll
            for (int c = 0; c < 5; c++) {
                float s = 0.f;
#pragma unroll
                for (int d = 0; d < 5; d++) s += u[a][d] * f[d] * u[c][d];
                sA5[a * 5 + c] = s;
            }

        // Reset scratch for the next graph replay
#pragma unroll
        for (int e = 0; e < 25; e++) g_M[e * 32] = 0.f;
        g_cnt = 0u;
    }
    __syncthreads();

    // ---- All 256 threads: H[a][j] = sum_b A5[a][b] * W2[b][j] -> g_H ----
    float a5[5][5];
#pragma unroll
    for (int a = 0; a < 5; a++)
#pragma unroll
        for (int c = 0; c < 5; c++) a5[a][c] = sA5[a * 5 + c];
#pragma unroll
    for (int k = 0; k < 8; k++) {
        const int j = tid + 256 * k;
        float w2j[5];
#pragma unroll
        for (int b2 = 0; b2 < 5; b2++) w2j[b2] = __ldg(W2 + b2 * 2048 + j);
#pragma unroll
        for (int a = 0; a < 5; a++) {
            float s = 0.f;
#pragma unroll
            for (int b2 = 0; b2 < 5; b2++) s += a5[a][b2] * w2j[b2];
            g_H[a * 2048 + j] = s;
        }
    }
}

// ---------------------------------------------------------------------------
// K2: z[i][j] = sum_a W2[a,i] * H[a,j] + EPS*(i==j)
// Prologue: 5 coalesced float4 loads of H (L2-resident). Row loop prefetch-
// pipelined; stores perfectly coalesced float4.
// ---------------------------------------------------------------------------
__global__ __launch_bounds__(256, 5) void k_out(const float* __restrict__ W2,
                                                float* __restrict__ out) {
    const int tid = threadIdx.x;
    const int j0  = blockIdx.x * 1024 + tid * 4;

    float4 h[5];
#pragma unroll
    for (int a = 0; a < 5; a++)
        h[a] = *reinterpret_cast<const float4*>(g_H + a * 2048 + j0);

    int i = blockIdx.y;
    float w[5];
#pragma unroll
    for (int a = 0; a < 5; a++) w[a] = __ldg(W2 + a * 2048 + i);

    while (true) {
        const int inx = i + 296;
        const bool more = (inx < 2048);
        float wn[5];
        if (more) {
#pragma unroll
            for (int a = 0; a < 5; a++) wn[a] = __ldg(W2 + a * 2048 + inx);
        }
        float4 v;
        v.x = w[0] * h[0].x; v.y = w[0] * h[0].y;
        v.z = w[0] * h[0].z; v.w = w[0] * h[0].w;
#pragma unroll
        for (int a = 1; a < 5; a++) {
            v.x += w[a] * h[a].x; v.y += w[a] * h[a].y;
            v.z += w[a] * h[a].z; v.w += w[a] * h[a].w;
        }
        const int d = i - j0;
        if ((unsigned)d < 4u) {
            if (d == 0) v.x += REPS;
            else if (d == 1) v.y += REPS;
            else if (d == 2) v.z += REPS;
            else v.w += REPS;
        }
        *reinterpret_cast<float4*>(out + (size_t)i * 2048 + j0) = v;
        if (!more) break;
        i = inx;
#pragma unroll
        for (int a = 0; a < 5; a++) w[a] = wn[a];
    }
}

// ---------------------------------------------------------------------------
extern "C" void kernel_launch(void* const* d_in, const int* in_sizes, int n_in,
                              void* d_out, int out_size) {
    const float* X  = (const float*)d_in[0];   // (1, 4096, 4096) f32
    const float* W1 = (const float*)d_in[1];   // (4096, 5) f32
    const float* W2 = (const float*)d_in[2];   // (5, 2048) f32
    float* out = (float*)d_out;                // (2048, 2048) f32

    k_proj<<<dim3(4, GYP), 256>>>(X, W1, W2);
    k_out <<<dim3(2, 296), 256>>>(W2, out);
}